// round 16
// baseline (speedup 1.0000x reference)
#include <cuda_runtime.h>

#define N_NODES   8192
#define T_TYPES   4
#define E_EDGES   131072
#define E_TOTAL   (T_TYPES * E_EDGES)   // 524288
#define H_HEADS   4
#define D_DIM     32
#define NEG_SLOPE 0.2f
#define WSTR      34                    // D_DIM + 2

// Lossy 4-bit counting table: 2^23 fields packed 8/word = 4 MiB
#define LSY_WORDS (1u << 20)
// Exact dup hash (true dups + ~6% lossy false positives, ~32K keys)
#define DUP_BITS  17
#define DUP_SIZE  (1u << DUP_BITS)
#define DUP_MASK  (DUP_SIZE - 1u)

#define EDGE_BLOCKS 512                 // 4 edges/thread (R12-proven)
#define FIN_BLOCKS   32                 // finalize (appended to K2)
#define CLR_L_BLOCKS 64                 // lossy-table clear (appended to K2)
#define K2_BLOCKS   (EDGE_BLOCKS + FIN_BLOCKS + CLR_L_BLOCKS)  // 608

// Scratch — zero-init at module load; self-cleaned every call.
__device__ unsigned int g_lsy[LSY_WORDS];
__device__ unsigned int g_dkey[DUP_SIZE];   // 0=empty else key+1 (cleared in K1)
__device__ unsigned int g_dcnt[DUP_SIZE];   // packed per-type byte counts
__device__ float4 g_acc[N_NODES * 2];       // [d0,n0,d1,n1][d2,n2,d3,n3]
__device__ float4 g_embT[T_TYPES];          // embterm[t] over 4 heads
__device__ float  g_part[32];               // score partial sums
__device__ unsigned int g_done;             // K2 edge-blocks-done counter
                                            // (reset by NEXT call's K1)

__device__ __forceinline__ unsigned int field_of(unsigned int key) {
    return (key * 0x9E3779B1u) >> 9;        // 23-bit field index
}

__device__ __forceinline__ float4 ld_cg_f4(const float4* p) {
    float4 v;
    asm volatile("ld.global.cg.v4.f32 {%0,%1,%2,%3}, [%4];"
                 : "=f"(v.x), "=f"(v.y), "=f"(v.z), "=f"(v.w) : "l"(p) : "memory");
    return v;
}

__device__ __forceinline__ float group_ex(
        unsigned int c, float si, float sj,
        float ws, float wt, float et0, float et1, float et2, float et3) {
    float c0 = (float)( c        & 0xFFu);
    float c1 = (float)((c >> 8 ) & 0xFFu);
    float c2 = (float)((c >> 16) & 0xFFu);
    float c3 = (float)((c >> 24) & 0xFFu);
    float a = (si * ws + sj * wt) * (c0 + c1 + c2 + c3)
            + c0 * et0 + c1 * et1 + c2 * et2 + c3 * et3;
    return __expf(fmaxf(a, NEG_SLOPE * a)) - 1.f;
}

// ---------------------------------------------------------------------------
// K1: lossy counting (fire-and-forget REDs) + prep + dup-hash clear folded
// into the latency bubbles + g_done reset for this call's K2. No sync.
// ---------------------------------------------------------------------------
__global__ void __launch_bounds__(256) k_count(
        const int*   __restrict__ ei,
        const float* __restrict__ scores,
        const float* __restrict__ emb,
        const float* __restrict__ W) {
    const int bid = blockIdx.x, tid = threadIdx.x;
    const int gtid = bid * 256 + tid;
    const int base = gtid * 4;              // 4 contiguous edges, same type t
    const int t = base >> 17, e = base & (E_EDGES - 1);

    int4 s4 = __ldg((const int4*)(ei + (t * 2    ) * E_EDGES + e));
    int4 t4 = __ldg((const int4*)(ei + (t * 2 + 1) * E_EDGES + e));

    unsigned int f[4];
    f[0] = field_of(((unsigned)s4.x << 13) | (unsigned)t4.x);
    f[1] = field_of(((unsigned)s4.y << 13) | (unsigned)t4.y);
    f[2] = field_of(((unsigned)s4.z << 13) | (unsigned)t4.z);
    f[3] = field_of(((unsigned)s4.w << 13) | (unsigned)t4.w);

    #pragma unroll
    for (int k = 0; k < 4; k++)
        asm volatile("red.global.add.u32 [%0], %1;"
                     :: "l"(&g_lsy[f[k] >> 3]),
                        "r"(1u << ((f[k] & 7u) * 4u)) : "memory");

    // clear dup hash (1 MB = 65536 uint4) across 512 blocks × 128 threads
    if (tid < 128) {
        unsigned int idx = (unsigned)bid * 128 + tid;
        uint4 z4 = make_uint4(0u, 0u, 0u, 0u);
        if (idx < 32768) ((uint4*)g_dkey)[idx] = z4;
        else             ((uint4*)g_dcnt)[idx - 32768] = z4;
    }

    if (bid < 32) {                         // per-block score partials
        __shared__ float red[256];
        red[tid] = __ldg(scores + bid * 256 + tid);
        __syncthreads();
        for (int o = 128; o > 0; o >>= 1) {
            if (tid < o) red[tid] += red[tid + o];
            __syncthreads();
        }
        if (tid == 0) g_part[bid] = red[0];
    } else if (bid == 32 && tid < T_TYPES) {
        float r[H_HEADS];
        #pragma unroll
        for (int h = 0; h < H_HEADS; h++) {
            float a = 0.f;
            #pragma unroll
            for (int d = 0; d < D_DIM; d++)
                a += __ldg(emb + tid * D_DIM + d) * __ldg(W + h * WSTR + 1 + d);
            r[h] = a;
        }
        g_embT[tid] = make_float4(r[0], r[1], r[2], r[3]);
    } else if (bid == 33 && tid == 0) {
        g_done = 0u;                        // safe: prev call's K2 fully done
    }
}

// ---------------------------------------------------------------------------
// K2: blocks [0,512): resolve edges (R12 body), then fence + release-add
//     to g_done.  Blocks [512,544): wait g_done==512, finalize + reset g_acc.
//     Blocks [544,608): wait g_done==512, clear lossy table.
// All 608 blocks co-resident (256thr, low regs) → waiters can't starve workers.
// ---------------------------------------------------------------------------
__global__ void __launch_bounds__(256) k_edges(
        const int*   __restrict__ ei,
        const float* __restrict__ scores,
        const float* __restrict__ W,
        float*       __restrict__ out) {
    const int bid = blockIdx.x, tid = threadIdx.x;

    if (bid < EDGE_BLOCKS) {
        const int gtid = bid * 256 + tid;
        const int base = gtid * 4;
        const int t = base >> 17, e = base & (E_EDGES - 1);

        int4 s4 = __ldg((const int4*)(ei + (t * 2    ) * E_EDGES + e));
        int4 t4 = __ldg((const int4*)(ei + (t * 2 + 1) * E_EDGES + e));

        unsigned int key[4], f[4], w[4];
        key[0] = ((unsigned)s4.x << 13) | (unsigned)t4.x;  f[0] = field_of(key[0]);
        key[1] = ((unsigned)s4.y << 13) | (unsigned)t4.y;  f[1] = field_of(key[1]);
        key[2] = ((unsigned)s4.z << 13) | (unsigned)t4.z;  f[2] = field_of(key[2]);
        key[3] = ((unsigned)s4.w << 13) | (unsigned)t4.w;  f[3] = field_of(key[3]);
        #pragma unroll
        for (int k = 0; k < 4; k++)
            w[k] = __ldg(&g_lsy[f[k] >> 3]);  // table read-only here → safe

        float4 embT = *(const float4*)&g_embT[t];
        float ws0 = __ldg(W + 0 * WSTR), wt0 = __ldg(W + 0 * WSTR + 33);
        float ws1 = __ldg(W + 1 * WSTR), wt1 = __ldg(W + 1 * WSTR + 33);
        float ws2 = __ldg(W + 2 * WSTR), wt2 = __ldg(W + 2 * WSTR + 33);
        float ws3 = __ldg(W + 3 * WSTR), wt3 = __ldg(W + 3 * WSTR + 33);

        #pragma unroll
        for (int k = 0; k < 4; k++) {
            unsigned int cnt = (w[k] >> ((f[k] & 7u) * 4u)) & 15u;
            unsigned int src = key[k] >> 13, tgt = key[k] & 8191u;
            float si = __ldg(scores + src);
            float sj = __ldg(scores + tgt);
            float ex0, ex1, ex2, ex3;

            if (cnt == 1u) {                // exact singleton (~94%)
                float a0 = si * ws0 + sj * wt0 + embT.x;
                float a1 = si * ws1 + sj * wt1 + embT.y;
                float a2 = si * ws2 + sj * wt2 + embT.z;
                float a3 = si * ws3 + sj * wt3 + embT.w;
                ex0 = __expf(fmaxf(a0, NEG_SLOPE * a0)) - 1.f;
                ex1 = __expf(fmaxf(a1, NEG_SLOPE * a1)) - 1.f;
                ex2 = __expf(fmaxf(a2, NEG_SLOPE * a2)) - 1.f;
                ex3 = __expf(fmaxf(a3, NEG_SLOPE * a3)) - 1.f;
            } else {                        // dup/collision: telescoping delta
                unsigned int hh = key[k] * 0x85EBCA6Bu;
                hh = (hh ^ (hh >> 16)) & DUP_MASK;
                while (true) {
                    unsigned int o = atomicCAS(&g_dkey[hh], 0u, key[k] + 1u);
                    if (o == 0u || o == key[k] + 1u) break;
                    hh = (hh + 1u) & DUP_MASK;
                }
                unsigned int inc   = 1u << (t * 8);
                unsigned int c_old = atomicAdd(&g_dcnt[hh], inc);
                unsigned int c_new = c_old + inc;
                float4 E0 = g_embT[0], E1 = g_embT[1];
                float4 E2 = g_embT[2], E3 = g_embT[3];
                ex0 = group_ex(c_new, si, sj, ws0, wt0, E0.x, E1.x, E2.x, E3.x)
                    - group_ex(c_old, si, sj, ws0, wt0, E0.x, E1.x, E2.x, E3.x);
                ex1 = group_ex(c_new, si, sj, ws1, wt1, E0.y, E1.y, E2.y, E3.y)
                    - group_ex(c_old, si, sj, ws1, wt1, E0.y, E1.y, E2.y, E3.y);
                ex2 = group_ex(c_new, si, sj, ws2, wt2, E0.z, E1.z, E2.z, E3.z)
                    - group_ex(c_old, si, sj, ws2, wt2, E0.z, E1.z, E2.z, E3.z);
                ex3 = group_ex(c_new, si, sj, ws3, wt3, E0.w, E1.w, E2.w, E3.w)
                    - group_ex(c_old, si, sj, ws3, wt3, E0.w, E1.w, E2.w, E3.w);
            }

            float4* dst = &g_acc[src * 2];
            asm volatile("red.global.add.v4.f32 [%0], {%1,%2,%3,%4};"
                         :: "l"(dst), "f"(ex0), "f"(ex0 * sj),
                            "f"(ex1), "f"(ex1 * sj) : "memory");
            asm volatile("red.global.add.v4.f32 [%0], {%1,%2,%3,%4};"
                         :: "l"(dst + 1), "f"(ex2), "f"(ex2 * sj),
                            "f"(ex3), "f"(ex3 * sj) : "memory");
        }

        // publish this block's REDs + table reads, then signal done
        __threadfence();
        __syncthreads();
        if (tid == 0)
            asm volatile("red.release.gpu.global.add.u32 [%0], %1;"
                         :: "l"(&g_done), "r"(1u) : "memory");
    } else {
        // waiter blocks: poll until all 512 edge blocks are done
        if (tid == 0) {
            unsigned int v;
            do {
                asm volatile("ld.acquire.gpu.global.u32 %0, [%1];"
                             : "=r"(v) : "l"(&g_done) : "memory");
            } while (v < (unsigned)EDGE_BLOCKS);
        }
        __syncthreads();

        if (bid < EDGE_BLOCKS + FIN_BLOCKS) {      // finalize
            float st = 0.f;
            #pragma unroll
            for (int k = 0; k < 32; k++) st += g_part[k];  // deterministic
            int i = (bid - EDGE_BLOCKS) * 256 + tid;
            float4 a0 = ld_cg_f4(&g_acc[i * 2]);
            float4 a1 = ld_cg_f4(&g_acc[i * 2 + 1]);
            out[i] = 0.25f * ((st + a0.y) / (8192.f + a0.x)
                            + (st + a0.w) / (8192.f + a0.z)
                            + (st + a1.y) / (8192.f + a1.x)
                            + (st + a1.w) / (8192.f + a1.z));
            g_acc[i * 2]     = make_float4(0.f, 0.f, 0.f, 0.f);
            g_acc[i * 2 + 1] = make_float4(0.f, 0.f, 0.f, 0.f);
        } else {                                    // clear lossy table (4 MB)
            uint4* l4 = (uint4*)g_lsy;              // 2^18 uint4
            uint4 z4 = make_uint4(0u, 0u, 0u, 0u);
            unsigned int b = (unsigned)(bid - EDGE_BLOCKS - FIN_BLOCKS) * 256 + tid;
            #pragma unroll
            for (int k = 0; k < 16; k++)
                l4[b + k * (CLR_L_BLOCKS * 256)] = z4;
        }
    }
}

// ---------------------------------------------------------------------------
extern "C" void kernel_launch(void* const* d_in, const int* in_sizes, int n_in,
                              void* d_out, int out_size) {
    const float* scores = (const float*)d_in[0];   // (N, 1)
    const float* emb    = (const float*)d_in[1];   // (T, D)
    const int*   ei     = (const int*)  d_in[2];   // (T, 2, E)
    const float* W      = (const float*)d_in[3];   // (H, D+2, 1)
    float*       out    = (float*)d_out;           // (N, 1)

    k_count<<<EDGE_BLOCKS, 256>>>(ei, scores, emb, W);
    k_edges<<<K2_BLOCKS,   256>>>(ei, scores, W, out);
}

// round 17
// speedup vs baseline: 1.5854x; 1.5854x over previous
#include <cuda_runtime.h>

#define N_NODES   8192
#define T_TYPES   4
#define E_EDGES   131072
#define E_TOTAL   (T_TYPES * E_EDGES)   // 524288
#define H_HEADS   4
#define D_DIM     32
#define NEG_SLOPE 0.2f
#define WSTR      34                    // D_DIM + 2

// Exact per-key table: 2^26 keys x 16 bits (4-bit count per edge type),
// packed 2 keys per u32 word. 128 MiB, zero-init at module load; touched
// sectors (~17MB) cleared each call by K2's edge re-stream.
#define TAB_WORDS (1u << 25)

#define EDGE_BLOCKS 512                 // 4 edges/thread
#define FIN_BLOCKS  32                  // finalize in K2
#define K2_BLOCKS   (FIN_BLOCKS + EDGE_BLOCKS)   // 544

__device__ unsigned int g_tab[TAB_WORDS];   // exact packed per-type counts
__device__ float4 g_acc[N_NODES * 2];       // [d0,n0,d1,n1][d2,n2,d3,n3]
__device__ float  g_part[32];               // score partial sums

// a(c) = (si*ws + sj*wt)*ctot + sum_t c_t*emb_t ; returns exp(leaky(a))-1.
// c is a 16-bit packed count (4 bits per type). group_ex(0) == 0 exactly.
__device__ __forceinline__ float group_ex(
        unsigned int c, float base,
        float et0, float et1, float et2, float et3) {
    float c0 = (float)( c        & 0xFu);
    float c1 = (float)((c >> 4 ) & 0xFu);
    float c2 = (float)((c >> 8 ) & 0xFu);
    float c3 = (float)((c >> 12) & 0xFu);
    float a = base * (c0 + c1 + c2 + c3)
            + c0 * et0 + c1 * et1 + c2 * et2 + c3 * et3;
    return __expf(fmaxf(a, NEG_SLOPE * a)) - 1.f;
}

// ---------------------------------------------------------------------------
// K1: single edge pass. Exact telescoping delta per edge via one
// atomicAdd-with-return on the direct-indexed table. Plus distributed prep.
// ---------------------------------------------------------------------------
__global__ void __launch_bounds__(256) k_edges(
        const int*   __restrict__ ei,
        const float* __restrict__ scores,
        const float* __restrict__ emb,
        const float* __restrict__ W) {
    const int bid = blockIdx.x, tid = threadIdx.x;
    const int gtid = bid * 256 + tid;
    const int base = gtid * 4;              // 4 contiguous edges, same type t
    const int t = base >> 17, e = base & (E_EDGES - 1);

    // per-block embterm[h][t] (tiny: 16 dot products of 32)
    __shared__ float s_emb[T_TYPES][H_HEADS];
    if (tid < 16) {
        int tt = tid >> 2, h = tid & 3;
        float a = 0.f;
        #pragma unroll
        for (int d = 0; d < D_DIM; d++)
            a += __ldg(emb + tt * D_DIM + d) * __ldg(W + h * WSTR + 1 + d);
        s_emb[tt][h] = a;
    }

    int4 s4 = __ldg((const int4*)(ei + (t * 2    ) * E_EDGES + e));
    int4 t4 = __ldg((const int4*)(ei + (t * 2 + 1) * E_EDGES + e));

    // score-sum partials (blocks 0..31), overlapped with edge work
    if (bid < 32) {
        __shared__ float red[256];
        red[tid] = __ldg(scores + bid * 256 + tid);
        __syncthreads();
        for (int o = 128; o > 0; o >>= 1) {
            if (tid < o) red[tid] += red[tid + o];
            __syncthreads();
        }
        if (tid == 0) g_part[bid] = red[0];
    }
    __syncthreads();                        // s_emb ready

    float ws0 = __ldg(W + 0 * WSTR), wt0 = __ldg(W + 0 * WSTR + 33);
    float ws1 = __ldg(W + 1 * WSTR), wt1 = __ldg(W + 1 * WSTR + 33);
    float ws2 = __ldg(W + 2 * WSTR), wt2 = __ldg(W + 2 * WSTR + 33);
    float ws3 = __ldg(W + 3 * WSTR), wt3 = __ldg(W + 3 * WSTR + 33);
    float e00 = s_emb[0][0], e10 = s_emb[1][0], e20 = s_emb[2][0], e30 = s_emb[3][0];
    float e01 = s_emb[0][1], e11 = s_emb[1][1], e21 = s_emb[2][1], e31 = s_emb[3][1];
    float e02 = s_emb[0][2], e12 = s_emb[1][2], e22 = s_emb[2][2], e32 = s_emb[3][2];
    float e03 = s_emb[0][3], e13 = s_emb[1][3], e23 = s_emb[2][3], e33 = s_emb[3][3];

    unsigned int srcA[4] = {(unsigned)s4.x, (unsigned)s4.y,
                            (unsigned)s4.z, (unsigned)s4.w};
    unsigned int tgtA[4] = {(unsigned)t4.x, (unsigned)t4.y,
                            (unsigned)t4.z, (unsigned)t4.w};
    const unsigned int inc4 = 1u << (4 * t);

    // issue all 4 independent atomics first (MLP=4 on the return path)
    unsigned int old[4], sh[4];
    #pragma unroll
    for (int k = 0; k < 4; k++) {
        unsigned int key = (srcA[k] << 13) | tgtA[k];
        sh[k] = (key & 1u) * 16u;
        old[k] = atomicAdd(&g_tab[key >> 1], inc4 << sh[k]);
    }

    #pragma unroll
    for (int k = 0; k < 4; k++) {
        unsigned int c_old = (old[k] >> sh[k]) & 0xFFFFu;
        unsigned int c_new = c_old + inc4;
        float si = __ldg(scores + srcA[k]);
        float sj = __ldg(scores + tgtA[k]);

        float ex0, ex1, ex2, ex3;
        float b0 = si * ws0 + sj * wt0;
        float b1 = si * ws1 + sj * wt1;
        float b2 = si * ws2 + sj * wt2;
        float b3 = si * ws3 + sj * wt3;
        if (c_old == 0u) {                  // first arrival (~99.6%)
            ex0 = group_ex(c_new, b0, e00, e10, e20, e30);
            ex1 = group_ex(c_new, b1, e01, e11, e21, e31);
            ex2 = group_ex(c_new, b2, e02, e12, e22, e32);
            ex3 = group_ex(c_new, b3, e03, e13, e23, e33);
        } else {                            // telescoping delta (exact)
            ex0 = group_ex(c_new, b0, e00, e10, e20, e30)
                - group_ex(c_old, b0, e00, e10, e20, e30);
            ex1 = group_ex(c_new, b1, e01, e11, e21, e31)
                - group_ex(c_old, b1, e01, e11, e21, e31);
            ex2 = group_ex(c_new, b2, e02, e12, e22, e32)
                - group_ex(c_old, b2, e02, e12, e22, e32);
            ex3 = group_ex(c_new, b3, e03, e13, e23, e33)
                - group_ex(c_old, b3, e03, e13, e23, e33);
        }

        float4* dst = &g_acc[srcA[k] * 2];
        asm volatile("red.global.add.v4.f32 [%0], {%1,%2,%3,%4};"
                     :: "l"(dst), "f"(ex0), "f"(ex0 * sj),
                        "f"(ex1), "f"(ex1 * sj) : "memory");
        asm volatile("red.global.add.v4.f32 [%0], {%1,%2,%3,%4};"
                     :: "l"(dst + 1), "f"(ex2), "f"(ex2 * sj),
                        "f"(ex3), "f"(ex3 * sj) : "memory");
    }
}

// ---------------------------------------------------------------------------
// K2: blocks [0,32) finalize + reset g_acc; blocks [32,544) clear the table
// by re-streaming edges and zeroing each touched word (benign all-zero race).
// ---------------------------------------------------------------------------
__global__ void __launch_bounds__(256) k_final(
        float* __restrict__ out,
        const int* __restrict__ ei) {
    const int bid = blockIdx.x, tid = threadIdx.x;

    if (bid < FIN_BLOCKS) {
        float st = 0.f;
        #pragma unroll
        for (int k = 0; k < 32; k++) st += g_part[k];   // deterministic order
        int i = bid * 256 + tid;
        float4 a0 = g_acc[i * 2];
        float4 a1 = g_acc[i * 2 + 1];
        out[i] = 0.25f * ((st + a0.y) / (8192.f + a0.x)
                        + (st + a0.w) / (8192.f + a0.z)
                        + (st + a1.y) / (8192.f + a1.x)
                        + (st + a1.w) / (8192.f + a1.z));
        g_acc[i * 2]     = make_float4(0.f, 0.f, 0.f, 0.f);
        g_acc[i * 2 + 1] = make_float4(0.f, 0.f, 0.f, 0.f);
    } else {
        const int gtid = (bid - FIN_BLOCKS) * 256 + tid;
        const int base = gtid * 4;
        const int t = base >> 17, e = base & (E_EDGES - 1);
        int4 s4 = __ldg((const int4*)(ei + (t * 2    ) * E_EDGES + e));
        int4 t4 = __ldg((const int4*)(ei + (t * 2 + 1) * E_EDGES + e));
        g_tab[(((unsigned)s4.x << 13) | (unsigned)t4.x) >> 1] = 0u;
        g_tab[(((unsigned)s4.y << 13) | (unsigned)t4.y) >> 1] = 0u;
        g_tab[(((unsigned)s4.z << 13) | (unsigned)t4.z) >> 1] = 0u;
        g_tab[(((unsigned)s4.w << 13) | (unsigned)t4.w) >> 1] = 0u;
    }
}

// ---------------------------------------------------------------------------
extern "C" void kernel_launch(void* const* d_in, const int* in_sizes, int n_in,
                              void* d_out, int out_size) {
    const float* scores = (const float*)d_in[0];   // (N, 1)
    const float* emb    = (const float*)d_in[1];   // (T, D)
    const int*   ei     = (const int*)  d_in[2];   // (T, 2, E)
    const float* W      = (const float*)d_in[3];   // (H, D+2, 1)
    float*       out    = (float*)d_out;           // (N, 1)

    k_edges<<<EDGE_BLOCKS, 256>>>(ei, scores, emb, W);
    k_final<<<K2_BLOCKS,   256>>>(out, ei);
}